// round 17
// baseline (speedup 1.0000x reference)
#include <cuda_runtime.h>
#include <cuda_fp16.h>
#include <cstdint>

#define DIM     768
#define HEADS   12
#define HD      64
#define BATCH   4
#define SEQ     2048
#define M_TOTAL (BATCH * SEQ)

// Q prescale: 0.125 (attn scale) * log2(e), folded into Q so softmax is bare ex2
#define QSCALE  0.18033688011112042f

// Scratch (static device globals: allocation-guard safe)
__device__ __half g_xh[M_TOTAL * DIM];
__device__ __half g_wq[DIM * DIM], g_wk[DIM * DIM], g_wv[DIM * DIM], g_wp[DIM * DIM];
__device__ __half g_q[M_TOTAL * DIM], g_k[M_TOTAL * DIM];
__device__ __half g_v[M_TOTAL * DIM], g_o[M_TOTAL * DIM];

__device__ __forceinline__ uint32_t smem_u32(const void* p) {
    uint32_t a;
    asm("{ .reg .u64 t; cvta.to.shared.u64 t, %1; cvt.u32.u64 %0, t; }"
        : "=r"(a) : "l"(p));
    return a;
}
__device__ __forceinline__ float ex2f(float x) {
    float r;
    asm("ex2.approx.f32 %0, %1;" : "=f"(r) : "f"(x));
    return r;
}

#define CP16(dst, src) \
    asm volatile("cp.async.cg.shared.global [%0], [%1], 16;\n" :: "r"(dst), "l"(src))
#define CPC()  asm volatile("cp.async.commit_group;\n" ::: "memory")
#define CPW2() asm volatile("cp.async.wait_group 2;\n" ::: "memory")
#define CPW1() asm volatile("cp.async.wait_group 1;\n" ::: "memory")
#define CPW0() asm volatile("cp.async.wait_group 0;\n" ::: "memory")

#define LDSM4(r0, r1, r2, r3, a)                                              \
    asm volatile("ldmatrix.sync.aligned.m8n8.x4.shared.b16 {%0,%1,%2,%3}, [%4];" \
        : "=r"(r0), "=r"(r1), "=r"(r2), "=r"(r3) : "r"(a))
#define LDSM4T(r0, r1, r2, r3, a)                                             \
    asm volatile("ldmatrix.sync.aligned.m8n8.x4.trans.shared.b16 {%0,%1,%2,%3}, [%4];" \
        : "=r"(r0), "=r"(r1), "=r"(r2), "=r"(r3) : "r"(a))

// D += A(16x16,row) * B(16x8,col) — fp16 inputs, fp32 accum
#define MMA_F16(d, a0, a1, a2, a3, b0, b1)                                    \
    asm volatile("mma.sync.aligned.m16n8k16.row.col.f32.f16.f16.f32 "         \
        "{%0,%1,%2,%3}, {%4,%5,%6,%7}, {%8,%9}, {%0,%1,%2,%3};"               \
        : "+f"((d).x), "+f"((d).y), "+f"((d).z), "+f"((d).w)                  \
        : "r"(a0), "r"(a1), "r"(a2), "r"(a3), "r"(b0), "r"(b1))

// Swizzled byte address: 128B rows, 8 chunks of 16B, chunk key = row&7
__device__ __forceinline__ uint32_t swad(uint32_t base, int row, int chk) {
    return base + row * 128 + ((chk ^ (row & 7)) << 4);
}

// ---------------------------------------------------------------------------
// fp32 -> fp16 conversion: 32B of halves per thread-iter (uint4 stores)
// ---------------------------------------------------------------------------
__global__ void cvt_half(const float* __restrict__ x,  const float* __restrict__ wq,
                         const float* __restrict__ wk, const float* __restrict__ wv,
                         const float* __restrict__ wp)
{
    const int NX = M_TOTAL * DIM / 8;
    const int NW = DIM * DIM / 8;
    int stride = gridDim.x * blockDim.x;
    for (int u = blockIdx.x * blockDim.x + threadIdx.x; u < NX + 4 * NW; u += stride) {
        const float* src; __half* dst; int off;
        if (u < NX) { src = x; dst = g_xh; off = u; }
        else {
            int w = (u - NX) / NW, r = (u - NX) % NW;
            src = (w == 0) ? wq : (w == 1) ? wk : (w == 2) ? wv : wp;
            dst = (w == 0) ? g_wq : (w == 1) ? g_wk : (w == 2) ? g_wv : g_wp;
            off = r;
        }
        float4 f0 = ((const float4*)src)[off * 2 + 0];
        float4 f1 = ((const float4*)src)[off * 2 + 1];
        __half2 h[4];
        h[0] = __floats2half2_rn(f0.x, f0.y);
        h[1] = __floats2half2_rn(f0.z, f0.w);
        h[2] = __floats2half2_rn(f1.x, f1.y);
        h[3] = __floats2half2_rn(f1.z, f1.w);
        ((uint4*)dst)[off] = *(uint4*)h;
    }
}

// ---------------------------------------------------------------------------
// QKV fp16 mma GEMM (R16, proven): 128x128 CTA tile, 4 warps (2x2),
// warp 64x64, BK=64, 3-slot cp.async ring, 128 threads, 2 CTAs/SM.
// half out; Q (z==0) prescaled by QSCALE.
// ---------------------------------------------------------------------------
__global__ void __launch_bounds__(128, 2) gemm_qkv(
    const __half* __restrict__ A,
    const __half* __restrict__ W0, const __half* __restrict__ W1,
    const __half* __restrict__ W2,
    __half* __restrict__ C0, __half* __restrict__ C1, __half* __restrict__ C2)
{
    extern __shared__ uint32_t smw[];

    const __half* W = W0;
    __half* C = C0;
    float osc = QSCALE;
    if (blockIdx.z == 1) { W = W1; C = C1; osc = 1.0f; }
    else if (blockIdx.z == 2) { W = W2; C = C2; osc = 1.0f; }

    const int tid = threadIdx.x, lane = tid & 31, warp = tid >> 5;
    const int wm = warp >> 1, wn = warp & 1;
    const int tg = lane & 3, gp = lane >> 2;
    const int l8 = lane & 7, lg = lane >> 3;
    const int bm = blockIdx.y * 128, bn = blockIdx.x * 128;
    const uint32_t base = smem_u32(smw);

    float4 acc[4][8];
    #pragma unroll
    for (int i = 0; i < 4; i++)
        #pragma unroll
        for (int j = 0; j < 8; j++) acc[i][j] = make_float4(0.f, 0.f, 0.f, 0.f);

    const int arow = wm * 64 + l8 + ((lg & 1) << 3);
    const int achk = lg >> 1;
    const int brow = wn * 64 + l8 + ((lg >> 1) << 3);
    const int bchk = lg & 1;

#define GSTAGE(SLOT, S) do {                                                   \
    int _k = (S) * 64;                                                         \
    uint32_t _ab = base + (SLOT) * 32768;                                      \
    _Pragma("unroll")                                                          \
    for (int _u = tid; _u < 1024; _u += 128) {                                 \
        int _r = _u >> 3, _g = _u & 7;                                         \
        uint32_t _d = _r * 128 + ((_g ^ (_r & 7)) << 4);                       \
        CP16(_ab + _d,         A + (size_t)(bm + _r) * DIM + _k + _g * 8);     \
        CP16(_ab + 16384 + _d, W + (size_t)(bn + _r) * DIM + _k + _g * 8);     \
    }                                                                          \
    CPC();                                                                     \
} while (0)

    GSTAGE(0, 0);
    GSTAGE(1, 1);

    for (int s = 0; s < 12; s++) {
        if (s + 1 < 12) CPW1(); else CPW0();
        __syncthreads();
        if (s + 2 < 12) GSTAGE((s + 2) % 3, s + 2);

        uint32_t Ab = base + (s % 3) * 32768;
        uint32_t Bb = Ab + 16384;
        #pragma unroll
        for (int kc = 0; kc < 4; kc++) {
            uint32_t a[4][4], b[4][4];
            #pragma unroll
            for (int mf = 0; mf < 4; mf++)
                LDSM4(a[mf][0], a[mf][1], a[mf][2], a[mf][3],
                      swad(Ab, arow + mf * 16, 2 * kc + achk));
            #pragma unroll
            for (int ng = 0; ng < 4; ng++)
                LDSM4(b[ng][0], b[ng][1], b[ng][2], b[ng][3],
                      swad(Bb, brow + ng * 16, 2 * kc + bchk));
            #pragma unroll
            for (int mf = 0; mf < 4; mf++)
                #pragma unroll
                for (int ng = 0; ng < 4; ng++) {
                    MMA_F16(acc[mf][2 * ng],     a[mf][0], a[mf][1], a[mf][2], a[mf][3],
                            b[ng][0], b[ng][1]);
                    MMA_F16(acc[mf][2 * ng + 1], a[mf][0], a[mf][1], a[mf][2], a[mf][3],
                            b[ng][2], b[ng][3]);
                }
        }
    }
#undef GSTAGE

    #pragma unroll
    for (int mf = 0; mf < 4; mf++) {
        int row = bm + wm * 64 + mf * 16 + gp;
        #pragma unroll
        for (int nf = 0; nf < 8; nf++) {
            int cc = bn + wn * 64 + nf * 8 + 2 * tg;
            *(__half2*)(C + (size_t)row * DIM + cc) =
                __floats2half2_rn(acc[mf][nf].x * osc, acc[mf][nf].y * osc);
            *(__half2*)(C + (size_t)(row + 8) * DIM + cc) =
                __floats2half2_rn(acc[mf][nf].z * osc, acc[mf][nf].w * osc);
        }
    }
}

// ---------------------------------------------------------------------------
// Output projection, flash-recipe: CTA 64x128, 4 warps, warp = 16 m-rows x
// 128 n (A-frag 1 LDSM4/kc reused across 16 MMAs, B addressing identical to
// flash's proven K path). BK=64, 2-slot ring (48KB), 4 CTAs/SM (~110 regs).
// Grid 768 CTAs = 1.3 waves of half-size tiles. fp32 out + bias.
// ---------------------------------------------------------------------------
__global__ void __launch_bounds__(128, 4) gemm_outf(
    const __half* __restrict__ A, const __half* __restrict__ W,
    const float* __restrict__ bias, float* __restrict__ C)
{
    extern __shared__ uint32_t smw[];   // 2 slots x (A 8KB | B 16KB) = 48KB
    const uint32_t base = smem_u32(smw);

    const int tid = threadIdx.x, lane = tid & 31, warp = tid >> 5;
    const int tg = lane & 3, gp = lane >> 2;
    const int l8 = lane & 7, lg = lane >> 3;
    const int bm = blockIdx.y * 64, bn = blockIdx.x * 128;

    float4 acc[16];
    #pragma unroll
    for (int j = 0; j < 16; j++) acc[j] = make_float4(0.f, 0.f, 0.f, 0.f);

    // A-frags: flash Q pattern (warp owns 16 m-rows)
    const int arow = warp * 16 + l8 + ((lg & 1) << 3);
    const int achk = lg >> 1;
    // B-frags: flash K pattern (+ng*16)
    const int brow = l8 + ((lg >> 1) << 3);
    const int bchk = lg & 1;

#define OSTAGE(SLOT, S) do {                                                   \
    int _k = (S) * 64;                                                         \
    uint32_t _ab = base + (SLOT) * 24576;                                      \
    _Pragma("unroll")                                                          \
    for (int _u = tid; _u < 512; _u += 128) {                                  \
        int _r = _u >> 3, _g = _u & 7;                                         \
        uint32_t _d = _r * 128 + ((_g ^ (_r & 7)) << 4);                       \
        CP16(_ab + _d, A + (size_t)(bm + _r) * DIM + _k + _g * 8);             \
    }                                                                          \
    _Pragma("unroll")                                                          \
    for (int _u = tid; _u < 1024; _u += 128) {                                 \
        int _r = _u >> 3, _g = _u & 7;                                         \
        uint32_t _d = _r * 128 + ((_g ^ (_r & 7)) << 4);                       \
        CP16(_ab + 8192 + _d, W + (size_t)(bn + _r) * DIM + _k + _g * 8);      \
    }                                                                          \
    CPC();                                                                     \
} while (0)

    OSTAGE(0, 0);

    for (int s = 0; s < 12; s++) {
        if (s + 1 < 12) { OSTAGE((s + 1) & 1, s + 1); CPW1(); }
        else            { CPW0(); }
        __syncthreads();

        uint32_t Ab = base + (s & 1) * 24576;
        uint32_t Bb = Ab + 8192;
        #pragma unroll
        for (int kc = 0; kc < 4; kc++) {
            uint32_t a[4];
            LDSM4(a[0], a[1], a[2], a[3], swad(Ab, arow, 2 * kc + achk));
            #pragma unroll
            for (int ng = 0; ng < 8; ng++) {
                uint32_t b[4];
                LDSM4(b[0], b[1], b[2], b[3],
                      swad(Bb, ng * 16 + brow, 2 * kc + bchk));
                MMA_F16(acc[2 * ng],     a[0], a[1], a[2], a[3], b[0], b[1]);
                MMA_F16(acc[2 * ng + 1], a[0], a[1], a[2], a[3], b[2], b[3]);
            }
        }
        __syncthreads();
    }
#undef OSTAGE

    int row = bm + warp * 16 + gp;
    #pragma unroll
    for (int nf = 0; nf < 16; nf++) {
        int cc = bn + nf * 8 + 2 * tg;
        float b0 = bias[cc], b1 = bias[cc + 1];
        *(float2*)(C + (size_t)row * DIM + cc) =
            make_float2(acc[nf].x + b0, acc[nf].y + b1);
        *(float2*)(C + (size_t)(row + 8) * DIM + cc) =
            make_float2(acc[nf].z + b0, acc[nf].w + b1);
    }
}

// ---------------------------------------------------------------------------
// fp16 mma flash attention (R16, proven): 64 q-rows/CTA, 4 warps x 16 rows,
// hoisted persistent Q frags, KV tile 64, 3-slot cp.async ring, 4 CTAs/SM.
// Q prescaled -> softmax p = ex2(s).
// ---------------------------------------------------------------------------
__global__ void __launch_bounds__(128, 4) flash_h(
    const __half* __restrict__ q, const __half* __restrict__ k,
    const __half* __restrict__ v, __half* __restrict__ o)
{
    extern __shared__ uint32_t smw[];
    const uint32_t base = smem_u32(smw);
    const uint32_t Qb = base;

    const int tid = threadIdx.x, lane = tid & 31, warp = tid >> 5;
    const int tg = lane & 3, gp = lane >> 2;
    const int l8 = lane & 7, lg = lane >> 3;
    const int h = blockIdx.y, b = blockIdx.z, q0 = blockIdx.x * 64;

    const int arow = warp * 16 + l8 + ((lg & 1) << 3);
    const int achk = lg >> 1;
    const int brow = l8 + ((lg >> 1) << 3);
    const int bchk = lg & 1;
    const int vrow = l8 + ((lg & 1) << 3);
    const int vchk = lg >> 1;

    // Q tile (cp.async group 0)
    const __half* qg = q + (size_t)(b * SEQ + q0) * DIM + h * HD;
    #pragma unroll
    for (int u = tid; u < 512; u += 128) {
        int r = u >> 3, g = u & 7;
        CP16(Qb + r * 128 + ((g ^ (r & 7)) << 4), qg + (size_t)r * DIM + g * 8);
    }
    CPC();

#define KVSTAGE(SLOT, T) do {                                                  \
    const __half* _kg = k + (size_t)(b * SEQ + (T) * 64) * DIM + h * HD;       \
    const __half* _vg = v + (size_t)(b * SEQ + (T) * 64) * DIM + h * HD;       \
    uint32_t _kb = base + 8192 + (SLOT) * 8192;                                \
    uint32_t _vb = base + 32768 + (SLOT) * 8192;                               \
    _Pragma("unroll")                                                          \
    for (int _u = tid; _u < 512; _u += 128) {                                  \
        int _r = _u >> 3, _g = _u & 7;                                         \
        uint32_t _d = _r * 128 + ((_g ^ (_r & 7)) << 4);                       \
        CP16(_kb + _d, _kg + (size_t)_r * DIM + _g * 8);                       \
        CP16(_vb + _d, _vg + (size_t)_r * DIM + _g * 8);                       \
    }                                                                          \
    CPC();                                                                     \
} while (0)

    KVSTAGE(0, 0);
    KVSTAGE(1, 1);

    // Hoisted one-time Q fragment load (wait: Q group done; 2 KV in flight)
    CPW2();
    __syncthreads();
    uint32_t qa[4][4];
    #pragma unroll
    for (int kc = 0; kc < 4; kc++)
        LDSM4(qa[kc][0], qa[kc][1], qa[kc][2], qa[kc][3],
              swad(Qb, arow, 2 * kc + achk));

    float4 oacc[8];
    float rs0 = 0.f, rs1 = 0.f;
    #pragma unroll
    for (int j = 0; j < 8; j++) oacc[j] = make_float4(0.f, 0.f, 0.f, 0.f);

    const int NT = SEQ / 64;
    for (int t = 0; t < NT; t++) {
        if (t + 1 < NT) CPW1(); else CPW0();
        __syncthreads();
        if (t + 2 < NT) KVSTAGE((t + 2) % 3, t + 2);

        uint32_t Kb = base + 8192 + (t % 3) * 8192;
        uint32_t Vb = base + 32768 + (t % 3) * 8192;

        float4 s[8];
        #pragma unroll
        for (int j = 0; j < 8; j++) s[j] = make_float4(0.f, 0.f, 0.f, 0.f);
        #pragma unroll
        for (int kc = 0; kc < 4; kc++) {
            uint32_t bb[4][4];
            #pragma unroll
            for (int ng = 0; ng < 4; ng++)
                LDSM4(bb[ng][0], bb[ng][1], bb[ng][2], bb[ng][3],
                      swad(Kb, ng * 16 + brow, 2 * kc + bchk));
            #pragma unroll
            for (int ng = 0; ng < 4; ng++) {
                MMA_F16(s[2 * ng],     qa[kc][0], qa[kc][1], qa[kc][2], qa[kc][3],
                        bb[ng][0], bb[ng][1]);
                MMA_F16(s[2 * ng + 1], qa[kc][0], qa[kc][1], qa[kc][2], qa[kc][3],
                        bb[ng][2], bb[ng][3]);
            }
        }

        uint32_t pa[8], pb[8];
        #pragma unroll
        for (int j = 0; j < 8; j++) {
            float px = ex2f(s[j].x);
            float py = ex2f(s[j].y);
            float pz = ex2f(s[j].z);
            float pw = ex2f(s[j].w);
            rs0 += px + py;
            rs1 += pz + pw;
            __half2 hA = __floats2half2_rn(px, py);
            __half2 hB = __floats2half2_rn(pz, pw);
            pa[j] = *(uint32_t*)&hA;
            pb[j] = *(uint32_t*)&hB;
        }

        #pragma unroll
        for (int kc = 0; kc < 4; kc++) {
            uint32_t vv[4][4];
            #pragma unroll
            for (int dg = 0; dg < 4; dg++)
                LDSM4T(vv[dg][0], vv[dg][1], vv[dg][2], vv[dg][3],
                       swad(Vb, kc * 16 + vrow, 2 * dg + vchk));
            #pragma unroll
            for (int dg = 0; dg < 4; dg++) {
                MMA_F16(oacc[2 * dg],     pa[2 * kc], pb[2 * kc],
                        pa[2 * kc + 1], pb[2 * kc + 1], vv[dg][0], vv[dg][1]);
                MMA_F16(oacc[2 * dg + 1], pa[2 * kc], pb[2 * kc],
                        pa[2 * kc + 1], pb[2 * kc + 1], vv[dg][2], vv[dg][3]);
            }
        }
    }
#undef KVSTAGE

    rs0 += __shfl_xor_sync(0xffffffffu, rs0, 1, 4);
    rs0 += __shfl_xor_sync(0xffffffffu, rs0, 2, 4);
    rs1 += __shfl_xor_sync(0xffffffffu, rs1, 1, 4);
    rs1 += __shfl_xor_sync(0xffffffffu, rs1, 2, 4);
    float i0 = 1.0f / rs0, i1 = 1.0f / rs1;

    __half* og = o + (size_t)(b * SEQ + q0 + warp * 16) * DIM + h * HD;
    #pragma unroll
    for (int j = 0; j < 8; j++) {
        int cc = 8 * j + 2 * tg;
        *(__half2*)(og + (size_t)gp * DIM + cc) =
            __floats2half2_rn(oacc[j].x * i0, oacc[j].y * i0);
        *(__half2*)(og + (size_t)(gp + 8) * DIM + cc) =
            __floats2half2_rn(oacc[j].z * i1, oacc[j].w * i1);
    }
}

// ---------------------------------------------------------------------------
extern "C" void kernel_launch(void* const* d_in, const int* in_sizes, int n_in,
                              void* d_out, int out_size)
{
    const float* x  = (const float*)d_in[0];
    const float* Wq = (const float*)d_in[1];
    const float* Wk = (const float*)d_in[2];
    const float* Wv = (const float*)d_in[3];
    const float* Wp = (const float*)d_in[4];
    const float* bp = (const float*)d_in[5];
    float* out = (float*)d_out;

    __half *xh, *wq, *wk, *wv, *wp, *qh, *kh, *vh, *oh;
    cudaGetSymbolAddress((void**)&xh, g_xh);
    cudaGetSymbolAddress((void**)&wq, g_wq);
    cudaGetSymbolAddress((void**)&wk, g_wk);
    cudaGetSymbolAddress((void**)&wv, g_wv);
    cudaGetSymbolAddress((void**)&wp, g_wp);
    cudaGetSymbolAddress((void**)&qh, g_q);
    cudaGetSymbolAddress((void**)&kh, g_k);
    cudaGetSymbolAddress((void**)&vh, g_v);
    cudaGetSymbolAddress((void**)&oh, g_o);

    const int qkv_smem   = 98304;   // 3 x 32KB
    const int outf_smem  = 49152;   // 2 x 24KB
    const int flash_smem = 57344;   // Q 8KB + 3x(K 8KB + V 8KB)
    cudaFuncSetAttribute(gemm_qkv,  cudaFuncAttributeMaxDynamicSharedMemorySize, qkv_smem);
    cudaFuncSetAttribute(gemm_outf, cudaFuncAttributeMaxDynamicSharedMemorySize, outf_smem);
    cudaFuncSetAttribute(flash_h,   cudaFuncAttributeMaxDynamicSharedMemorySize, flash_smem);

    cvt_half<<<4096, 256>>>(x, Wq, Wk, Wv, Wp);

    dim3 gQKV(DIM / 128, M_TOTAL / 128, 3);   // (6, 64, 3)
    gemm_qkv<<<gQKV, 128, qkv_smem>>>(xh, wq, wk, wv, qh, kh, vh);

    dim3 gF(SEQ / 64, HEADS, BATCH);          // (32, 12, 4)
    flash_h<<<gF, 128, flash_smem>>>(qh, kh, vh, oh);

    dim3 gO(DIM / 128, M_TOTAL / 64);         // (6, 128) = 768 CTAs
    gemm_outf<<<gO, 128, outf_smem>>>(oh, wp, bp, out);
}